// round 5
// baseline (speedup 1.0000x reference)
#include <cuda_runtime.h>

typedef unsigned long long ull;

#define SEQ 4096
#define HID 1024
#define G4H 4096
#define NCTA 128
#define SENT 0x7FC0DEADu   // NaN payload sentinel: h = o*tanh(c) is never NaN

// ---------------- device scratch (no runtime allocations allowed) ----------------
__device__ float g_xg[(size_t)SEQ * G4H];   // 64 MB precomputed input-gate contributions
__device__ float g_hs[(size_t)SEQ * HID];   // 16 MB hidden states (sentinel-filled per replay)
__device__ float g_weff[HID];
__device__ float g_beff;

// ---------------- helpers ----------------
__device__ __forceinline__ void ffma2(ull &d, ull a, ull b) {
    asm("fma.rn.f32x2 %0, %1, %2, %0;" : "+l"(d) : "l"(a), "l"(b));
}
__device__ __forceinline__ ull dup2(float x) {
    ull r; asm("mov.b64 %0, {%1, %1};" : "=l"(r) : "f"(x)); return r;
}
__device__ __forceinline__ float2 unp(ull v) {
    float2 r; asm("mov.b64 {%0, %1}, %2;" : "=f"(r.x), "=f"(r.y) : "l"(v)); return r;
}
__device__ __forceinline__ float sigf(float x) {
    return 1.f / (1.f + __expf(-x));
}
__device__ __forceinline__ float tanh_(float x) {
    float e = __expf(-2.f * fabsf(x));
    float t = (1.f - e) / (1.f + e);
    return copysignf(t, x);
}

// ---------------- sentinel fill of g_hs (per graph replay) ----------------
__global__ __launch_bounds__(256) void sent_kernel() {
    uint4 s = make_uint4(SENT, SENT, SENT, SENT);
    uint4* p = (uint4*)g_hs;
    int n = (SEQ * HID) / 4;                  // 1M uint4
    for (int i = blockIdx.x * 256 + threadIdx.x; i < n; i += gridDim.x * 256)
        p[i] = s;
}

// ---------------- x_gates GEMM: [S,4H] = emb[sent] @ W_ih^T + (b_ih+b_hh) ----
__global__ __launch_bounds__(256, 1) void gemm_kernel(
    const int* __restrict__ sent, const float* __restrict__ emb,
    const float* __restrict__ Wih, const float* __restrict__ bih,
    const float* __restrict__ bhh)
{
    __shared__ __align__(16) float As[16][132];
    __shared__ __align__(16) float Bs[16][132];
    __shared__ int ss[128];

    int tid = threadIdx.x;
    int bn = blockIdx.x * 128;   // gate dim
    int bs = blockIdx.y * 128;   // seq dim
    if (tid < 128) ss[tid] = sent[bs + tid];
    __syncthreads();

    ull acc[8][4] = {};
    int tx = tid & 15, ty = tid >> 4;
    int m0 = ty * 8, n0 = tx * 8;

    for (int k0 = 0; k0 < 1024; k0 += 16) {
#pragma unroll
        for (int p = 0; p < 2; p++) {
            int idx = p * 256 + tid;
            int row = idx >> 2, kq = idx & 3;
            float4 av = *(const float4*)(emb + (size_t)ss[row] * 1024 + k0 + kq * 4);
            As[kq*4+0][row] = av.x; As[kq*4+1][row] = av.y;
            As[kq*4+2][row] = av.z; As[kq*4+3][row] = av.w;
            float4 bv = *(const float4*)(Wih + (size_t)(bn + row) * 1024 + k0 + kq * 4);
            Bs[kq*4+0][row] = bv.x; Bs[kq*4+1][row] = bv.y;
            Bs[kq*4+2][row] = bv.z; Bs[kq*4+3][row] = bv.w;
        }
        __syncthreads();
#pragma unroll
        for (int kk = 0; kk < 16; kk++) {
            float4 aA = *(const float4*)(&As[kk][m0]);
            float4 aB = *(const float4*)(&As[kk][m0 + 4]);
            ulonglong2 b01 = *(const ulonglong2*)(&Bs[kk][n0]);
            ulonglong2 b23 = *(const ulonglong2*)(&Bs[kk][n0 + 4]);
            ull bp0 = b01.x, bp1 = b01.y, bp2 = b23.x, bp3 = b23.y;
            float a[8] = {aA.x, aA.y, aA.z, aA.w, aB.x, aB.y, aB.z, aB.w};
#pragma unroll
            for (int i = 0; i < 8; i++) {
                ull ad = dup2(a[i]);
                ffma2(acc[i][0], ad, bp0);
                ffma2(acc[i][1], ad, bp1);
                ffma2(acc[i][2], ad, bp2);
                ffma2(acc[i][3], ad, bp3);
            }
        }
        __syncthreads();
    }

    float bb[8];
#pragma unroll
    for (int j = 0; j < 8; j++) bb[j] = bih[bn + n0 + j] + bhh[bn + n0 + j];
#pragma unroll
    for (int i = 0; i < 8; i++) {
        float* crow = g_xg + (size_t)(bs + m0 + i) * G4H + bn + n0;
        float2 r0 = unp(acc[i][0]), r1 = unp(acc[i][1]);
        float2 r2 = unp(acc[i][2]), r3 = unp(acc[i][3]);
        float4 v0 = make_float4(r0.x + bb[0], r0.y + bb[1], r1.x + bb[2], r1.y + bb[3]);
        float4 v1 = make_float4(r2.x + bb[4], r2.y + bb[5], r3.x + bb[6], r3.y + bb[7]);
        __stcs((float4*)crow, v0);           // streamed: read exactly once later
        __stcs((float4*)(crow + 4), v1);
    }
}

// ---------------- fold hybrid head: w_eff = W_hyb @ W_tag ----------------
__global__ void weff_kernel(const float* __restrict__ Wtag, const float* __restrict__ btag,
                            const float* __restrict__ Whyb, const float* __restrict__ bhyb)
{
    int h = blockIdx.x * 256 + threadIdx.x;
    float acc = 0.f;
    for (int t = 0; t < 1024; t++) acc += Whyb[t] * Wtag[(size_t)t * 1024 + h];
    g_weff[h] = acc;
    if (h == 0) {
        float b = bhyb[0];
        for (int t = 0; t < 1024; t++) b += Whyb[t] * btag[t];
        g_beff = b;
    }
}

// ---------------- persistent LSTM recurrence (dataflow-synchronized) ----------------
// 128 CTAs (<= 148 SMs -> all co-resident). CTA c owns hidden units [8c,8c+8).
// Warp w owns unit 8c+w: lane = gate(2b) x K-chunk(3b). 128 W_hh weights per
// thread in registers (64 x f32x2). NO global barrier: g_hs is pre-filled with
// a NaN sentinel; each consumer thread volatile-polls the exact float4 of
// h[t-1] it must stage, so detection IS the load. Double-buffered SMEM stage
// -> exactly one __syncthreads per step (slip within a CTA bounded by the bar,
// so buffer reuse at t+2 cannot race step-t readers).
__global__ __launch_bounds__(256, 1) void lstm_kernel(const float* __restrict__ Whh)
{
    __shared__ __align__(16) float sh_h[2][8 * 132];

    int tid  = threadIdx.x, cta = blockIdx.x;
    int warp = tid >> 5, lane = tid & 31;
    int g    = lane >> 3;          // gate: 0=i 1=f 2=g 3=o
    int kc   = lane & 7;           // K chunk (128 floats each)
    int unit = cta * 8 + warp;
    int wrow = g * 1024 + unit;    // row in W_hh / column in x_gates

    // load this thread's 128 weights into registers (one time)
    ull w[64];
    {
        const ulonglong2* wp = (const ulonglong2*)(Whh + (size_t)wrow * 1024 + kc * 128);
#pragma unroll
        for (int j = 0; j < 32; j++) { ulonglong2 t = wp[j]; w[2*j] = t.x; w[2*j+1] = t.y; }
    }

    const float* xp = g_xg + wrow;   // advance by 4096 per step
    float c = 0.f;                   // cell state, lane 0 of each warp
    float* sstore = sh_h[0] + (tid >> 5) * 132 + (tid & 31) * 4;

    for (int t = 0; t < SEQ; t++) {
        // prefetch input-gate contribution (.cs: streamed once, spare L2)
        float xgv = 0.f;
        if (kc == 0)
            asm("ld.global.cs.f32 %0, [%1];" : "=f"(xgv) : "l"(xp));
        xp += G4H;

        float dot = 0.f;
        if (t > 0) {
            int buf = t & 1;
            // poll-on-data: wait for the exact 4 h values this thread stages
            const float* hp_g = g_hs + (size_t)(t - 1) * HID + tid * 4;
            uint4 u;
            do {
                asm volatile("ld.volatile.global.v4.b32 {%0,%1,%2,%3}, [%4];"
                             : "=r"(u.x), "=r"(u.y), "=r"(u.z), "=r"(u.w)
                             : "l"(hp_g));
            } while (u.x == SENT || u.y == SENT || u.z == SENT || u.w == SENT);
            *(uint4*)(sstore + buf * (8 * 132)) = u;
            __syncthreads();

            const ulonglong2* hp = (const ulonglong2*)(sh_h[buf] + kc * 132);
            ull a0 = 0, a1 = 0, a2 = 0, a3 = 0;
#pragma unroll
            for (int j = 0; j < 32; j += 2) {
                ulonglong2 h0 = hp[j];
                ulonglong2 h1 = hp[j + 1];
                ffma2(a0, w[2*j],     h0.x);
                ffma2(a1, w[2*j + 1], h0.y);
                ffma2(a2, w[2*j + 2], h1.x);
                ffma2(a3, w[2*j + 3], h1.y);
            }
            float2 f0 = unp(a0), f1 = unp(a1), f2 = unp(a2), f3 = unp(a3);
            dot = ((f0.x + f0.y) + (f1.x + f1.y)) + ((f2.x + f2.y) + (f3.x + f3.y));
        }

        // reduce across the 8 K-chunk lanes (consecutive lanes within the warp)
        dot += __shfl_xor_sync(0xffffffffu, dot, 1);
        dot += __shfl_xor_sync(0xffffffffu, dot, 2);
        dot += __shfl_xor_sync(0xffffffffu, dot, 4);
        dot += xgv;   // nonzero only on kc==0 lanes

        // parallel gate activation: lanes 0,8,24 -> sigmoid, lane 16 -> tanh
        float act = (lane == 16) ? tanh_(dot) : sigf(dot);

        // gather activated gates into lane 0
        float a_f = __shfl_sync(0xffffffffu, act, 8);
        float a_g = __shfl_sync(0xffffffffu, act, 16);
        float a_o = __shfl_sync(0xffffffffu, act, 24);

        if (lane == 0) {
            c = a_f * c + act * a_g;           // act = sigmoid(i) in lane 0
            float h = a_o * tanh_(c);
            // publish: plain 4B word write; consumers detect non-sentinel
            asm volatile("st.volatile.global.f32 [%0], %1;"
                         :: "l"(g_hs + (size_t)t * HID + unit), "f"(h));
        }
        // no trailing barrier: next step writes the OTHER smem buffer
    }
}

// ---------------- output head: sigmoid(hs . w_eff + b_eff) ----------------
__global__ __launch_bounds__(256) void head_kernel(float* __restrict__ out)
{
    int warp = (blockIdx.x * 256 + threadIdx.x) >> 5;
    int lane = threadIdx.x & 31;
    const float* hrow = g_hs + (size_t)warp * HID;
    float acc = 0.f;
#pragma unroll
    for (int i = 0; i < 32; i++) acc += hrow[lane + 32 * i] * g_weff[lane + 32 * i];
#pragma unroll
    for (int o = 16; o; o >>= 1) acc += __shfl_xor_sync(0xffffffffu, acc, o);
    if (lane == 0) out[warp] = sigf(acc + g_beff);
}

// ---------------- launcher ----------------
extern "C" void kernel_launch(void* const* d_in, const int* in_sizes, int n_in,
                              void* d_out, int out_size)
{
    const int*   sent = (const int*)d_in[0];
    const float* emb  = (const float*)d_in[1];
    const float* Wih  = (const float*)d_in[2];
    const float* Whh  = (const float*)d_in[3];
    const float* bih  = (const float*)d_in[4];
    const float* bhh  = (const float*)d_in[5];
    const float* Wtag = (const float*)d_in[6];
    const float* btag = (const float*)d_in[7];
    const float* Whyb = (const float*)d_in[8];
    const float* bhyb = (const float*)d_in[9];

    sent_kernel<<<256, 256>>>();                       // re-sentinel g_hs each replay
    gemm_kernel<<<dim3(32, 32), 256>>>(sent, emb, Wih, bih, bhh);
    weff_kernel<<<4, 256>>>(Wtag, btag, Whyb, bhyb);
    lstm_kernel<<<NCTA, 256>>>(Whh);
    head_kernel<<<512, 256>>>((float*)d_out);
}

// round 9
// speedup vs baseline: 1.8740x; 1.8740x over previous
#include <cuda_runtime.h>

typedef unsigned long long ull;

#define SEQ 4096
#define HID 1024
#define G4H 4096
#define NCTA 128
#define NREP 16
#define SENT 0x7FC0DEADu   // NaN payload sentinel: h = o*tanh(c) is never NaN

// ---------------- device scratch (no runtime allocations allowed) ----------------
__device__ float g_xg[(size_t)SEQ * G4H];          // 64 MB precomputed input-gate contributions
__device__ float g_hrep[NREP][(size_t)SEQ * HID];  // 256 MB: 16 replicas of hidden states
__device__ float g_weff[HID];
__device__ float g_beff;

// ---------------- helpers ----------------
__device__ __forceinline__ void ffma2(ull &d, ull a, ull b) {
    asm("fma.rn.f32x2 %0, %1, %2, %0;" : "+l"(d) : "l"(a), "l"(b));
}
__device__ __forceinline__ ull dup2(float x) {
    ull r; asm("mov.b64 %0, {%1, %1};" : "=l"(r) : "f"(x)); return r;
}
__device__ __forceinline__ float2 unp(ull v) {
    float2 r; asm("mov.b64 {%0, %1}, %2;" : "=f"(r.x), "=f"(r.y) : "l"(v)); return r;
}
__device__ __forceinline__ float sigf(float x) {
    return 1.f / (1.f + __expf(-x));
}
__device__ __forceinline__ float tanh_(float x) {
    float e = __expf(-2.f * fabsf(x));
    float t = (1.f - e) / (1.f + e);
    return copysignf(t, x);
}

// ---------------- sentinel fill of all h replicas (per graph replay) ----------------
__global__ __launch_bounds__(256) void sent_kernel() {
    float4 s;
    s.x = s.y = s.z = s.w = __uint_as_float(SENT);
    float4* p = (float4*)g_hrep;
    int n = (NREP * SEQ * HID) / 4;               // 16M float4 = 256 MB
    for (int i = blockIdx.x * 256 + threadIdx.x; i < n; i += gridDim.x * 256)
        __stcs(p + i, s);                          // streaming store: don't pollute L2
}

// ---------------- x_gates GEMM: [S,4H] = emb[sent] @ W_ih^T + (b_ih+b_hh) ----
__global__ __launch_bounds__(256, 1) void gemm_kernel(
    const int* __restrict__ sent, const float* __restrict__ emb,
    const float* __restrict__ Wih, const float* __restrict__ bih,
    const float* __restrict__ bhh)
{
    __shared__ __align__(16) float As[16][132];
    __shared__ __align__(16) float Bs[16][132];
    __shared__ int ss[128];

    int tid = threadIdx.x;
    int bn = blockIdx.x * 128;   // gate dim
    int bs = blockIdx.y * 128;   // seq dim
    if (tid < 128) ss[tid] = sent[bs + tid];
    __syncthreads();

    ull acc[8][4] = {};
    int tx = tid & 15, ty = tid >> 4;
    int m0 = ty * 8, n0 = tx * 8;

    for (int k0 = 0; k0 < 1024; k0 += 16) {
#pragma unroll
        for (int p = 0; p < 2; p++) {
            int idx = p * 256 + tid;
            int row = idx >> 2, kq = idx & 3;
            float4 av = *(const float4*)(emb + (size_t)ss[row] * 1024 + k0 + kq * 4);
            As[kq*4+0][row] = av.x; As[kq*4+1][row] = av.y;
            As[kq*4+2][row] = av.z; As[kq*4+3][row] = av.w;
            float4 bv = *(const float4*)(Wih + (size_t)(bn + row) * 1024 + k0 + kq * 4);
            Bs[kq*4+0][row] = bv.x; Bs[kq*4+1][row] = bv.y;
            Bs[kq*4+2][row] = bv.z; Bs[kq*4+3][row] = bv.w;
        }
        __syncthreads();
#pragma unroll
        for (int kk = 0; kk < 16; kk++) {
            float4 aA = *(const float4*)(&As[kk][m0]);
            float4 aB = *(const float4*)(&As[kk][m0 + 4]);
            ulonglong2 b01 = *(const ulonglong2*)(&Bs[kk][n0]);
            ulonglong2 b23 = *(const ulonglong2*)(&Bs[kk][n0 + 4]);
            ull bp0 = b01.x, bp1 = b01.y, bp2 = b23.x, bp3 = b23.y;
            float a[8] = {aA.x, aA.y, aA.z, aA.w, aB.x, aB.y, aB.z, aB.w};
#pragma unroll
            for (int i = 0; i < 8; i++) {
                ull ad = dup2(a[i]);
                ffma2(acc[i][0], ad, bp0);
                ffma2(acc[i][1], ad, bp1);
                ffma2(acc[i][2], ad, bp2);
                ffma2(acc[i][3], ad, bp3);
            }
        }
        __syncthreads();
    }

    float bb[8];
#pragma unroll
    for (int j = 0; j < 8; j++) bb[j] = bih[bn + n0 + j] + bhh[bn + n0 + j];
#pragma unroll
    for (int i = 0; i < 8; i++) {
        float* crow = g_xg + (size_t)(bs + m0 + i) * G4H + bn + n0;
        float2 r0 = unp(acc[i][0]), r1 = unp(acc[i][1]);
        float2 r2 = unp(acc[i][2]), r3 = unp(acc[i][3]);
        float4 v0 = make_float4(r0.x + bb[0], r0.y + bb[1], r1.x + bb[2], r1.y + bb[3]);
        float4 v1 = make_float4(r2.x + bb[4], r2.y + bb[5], r3.x + bb[6], r3.y + bb[7]);
        __stcs((float4*)crow, v0);           // streamed: read exactly once later
        __stcs((float4*)(crow + 4), v1);
    }
}

// ---------------- fold hybrid head: w_eff = W_hyb @ W_tag ----------------
__global__ void weff_kernel(const float* __restrict__ Wtag, const float* __restrict__ btag,
                            const float* __restrict__ Whyb, const float* __restrict__ bhyb)
{
    int h = blockIdx.x * 256 + threadIdx.x;
    float acc = 0.f;
    for (int t = 0; t < 1024; t++) acc += Whyb[t] * Wtag[(size_t)t * 1024 + h];
    g_weff[h] = acc;
    if (h == 0) {
        float b = bhyb[0];
        for (int t = 0; t < 1024; t++) b += Whyb[t] * btag[t];
        g_beff = b;
    }
}

// ---------------- persistent LSTM recurrence (replicated dataflow sync) -----------
// 128 CTAs (<= 148 SMs -> all co-resident). CTA c owns hidden units [8c,8c+8).
// Warp w owns unit 8c+w: lane = gate(2b) x K-chunk(3b). 128 W_hh weights per
// thread in registers. No global barrier: writers publish each h to 16 replica
// arrays IN PARALLEL (lanes 0-15, one replica each, single STG instruction);
// consumer CTA c volatile-polls ONLY replica c&15 -> per-128B-line fan-in is
// 64 pollers (~4 B/cyc/line, ~4x headroom below the ~34 B/cyc LTS slice
// service rate; R5's single-array scheme hit ~130 B/cyc/slice and collapsed
// to 17.4ms). Detection IS the data fetch. Gate math runs redundantly in all
// 32 lanes (value-uniform per 8-lane group after the xor-reduce) with a
// branch-free sigmoid/tanh skeleton. Double-buffered SMEM stage -> exactly
// one __syncthreads per step.
__global__ __launch_bounds__(256, 1) void lstm_kernel(const float* __restrict__ Whh)
{
    __shared__ __align__(16) float sh_h[2][8 * 132];

    int tid  = threadIdx.x, cta = blockIdx.x;
    int warp = tid >> 5, lane = tid & 31;
    int g    = lane >> 3;          // gate: 0=i 1=f 2=g 3=o
    int kc   = lane & 7;           // K chunk (128 floats each)
    int unit = cta * 8 + warp;
    int wrow = g * 1024 + unit;    // row in W_hh / column in x_gates

    // load this thread's 128 weights into registers (one time)
    ull w[64];
    {
        const ulonglong2* wp = (const ulonglong2*)(Whh + (size_t)wrow * 1024 + kc * 128);
#pragma unroll
        for (int j = 0; j < 32; j++) { ulonglong2 t = wp[j]; w[2*j] = t.x; w[2*j+1] = t.y; }
    }

    const float* xp   = g_xg + wrow;            // same addr for all 8 lanes of a group
    const float* prep = g_hrep[cta & (NREP-1)] + tid * 4;   // this thread's poll quad
    float c = 0.f;                              // cell state (uniform across warp)
    float* sstore = sh_h[0] + (tid >> 5) * 132 + (tid & 31) * 4;
    // branch-free activation constants: gate g (lane group 2) uses tanh(x)
    // = signed (1-e^{-2|x|})/(1+e^{-2|x|}); others sigmoid(x) = 0.5*(1+tanh(x/2))
    float escale = (g == 2) ? -2.f : -1.f;
    float amul   = (g == 2) ? 1.f : 0.5f;
    float aadd   = (g == 2) ? 0.f : 0.5f;

    for (int t = 0; t < SEQ; t++) {
        // input-gate contribution, loaded on ALL lanes (broadcast within each
        // gate group, one wavefront); .cs: streamed once, spare L2
        float xgv;
        asm("ld.global.cs.f32 %0, [%1];" : "=f"(xgv) : "l"(xp));
        xp += G4H;

        float dot = 0.f;
        if (t > 0) {
            int buf = t & 1;
            // poll-on-data in our private replica: wait for the exact 4 h
            // values this thread stages
            const float* hp_g = prep + (size_t)(t - 1) * HID;
            uint4 u;
            do {
                asm volatile("ld.volatile.global.v4.b32 {%0,%1,%2,%3}, [%4];"
                             : "=r"(u.x), "=r"(u.y), "=r"(u.z), "=r"(u.w)
                             : "l"(hp_g));
            } while (u.x == SENT || u.y == SENT || u.z == SENT || u.w == SENT);
            *(uint4*)(sstore + buf * (8 * 132)) = u;
            __syncthreads();

            const ulonglong2* hp = (const ulonglong2*)(sh_h[buf] + kc * 132);
            ull a0 = 0, a1 = 0, a2 = 0, a3 = 0;
#pragma unroll
            for (int j = 0; j < 32; j += 2) {
                ulonglong2 h0 = hp[j];
                ulonglong2 h1 = hp[j + 1];
                ffma2(a0, w[2*j],     h0.x);
                ffma2(a1, w[2*j + 1], h0.y);
                ffma2(a2, w[2*j + 2], h1.x);
                ffma2(a3, w[2*j + 3], h1.y);
            }
            float2 f0 = unp(a0), f1 = unp(a1), f2 = unp(a2), f3 = unp(a3);
            dot = ((f0.x + f0.y) + (f1.x + f1.y)) + ((f2.x + f2.y) + (f3.x + f3.y));
        }

        // reduce across the 8 K-chunk lanes; afterwards every lane of a gate
        // group holds the full gate pre-activation
        dot += __shfl_xor_sync(0xffffffffu, dot, 1);
        dot += __shfl_xor_sync(0xffffffffu, dot, 2);
        dot += __shfl_xor_sync(0xffffffffu, dot, 4);
        dot += xgv;

        // branch-free activation (uniform within each 8-lane gate group):
        //   r = signed (1-e)/(1+e), e = exp(escale*|dot|);  act = amul*r + aadd
        float e = __expf(escale * fabsf(dot));
        float r = copysignf((1.f - e) / (1.f + e), dot);
        float act = fmaf(amul, r, aadd);

        // gather the 4 gate activations (any lane of each group is valid)
        float a_i = __shfl_sync(0xffffffffu, act, kc);
        float a_f = __shfl_sync(0xffffffffu, act, kc + 8);
        float a_g = __shfl_sync(0xffffffffu, act, kc + 16);
        float a_o = __shfl_sync(0xffffffffu, act, kc + 24);

        // cell update, redundantly in all lanes (identical values)
        c = a_f * c + a_i * a_g;
        float h = a_o * tanh_(c);

        // publish: lanes 0-15 store to their replica in parallel (one STG)
        if (lane < NREP) {
            asm volatile("st.volatile.global.f32 [%0], %1;"
                         :: "l"(&g_hrep[lane][(size_t)t * HID + unit]), "f"(h));
        }
        // no trailing barrier: next step writes the OTHER smem buffer
    }
}

// ---------------- output head: sigmoid(hs . w_eff + b_eff) ----------------
__global__ __launch_bounds__(256) void head_kernel(float* __restrict__ out)
{
    int warp = (blockIdx.x * 256 + threadIdx.x) >> 5;
    int lane = threadIdx.x & 31;
    const float* hrow = g_hrep[0] + (size_t)warp * HID;
    float acc = 0.f;
#pragma unroll
    for (int i = 0; i < 32; i++) acc += hrow[lane + 32 * i] * g_weff[lane + 32 * i];
#pragma unroll
    for (int o = 16; o; o >>= 1) acc += __shfl_xor_sync(0xffffffffu, acc, o);
    if (lane == 0) out[warp] = sigf(acc + g_beff);
}

// ---------------- launcher ----------------
extern "C" void kernel_launch(void* const* d_in, const int* in_sizes, int n_in,
                              void* d_out, int out_size)
{
    const int*   sent = (const int*)d_in[0];
    const float* emb  = (const float*)d_in[1];
    const float* Wih  = (const float*)d_in[2];
    const float* Whh  = (const float*)d_in[3];
    const float* bih  = (const float*)d_in[4];
    const float* bhh  = (const float*)d_in[5];
    const float* Wtag = (const float*)d_in[6];
    const float* btag = (const float*)d_in[7];
    const float* Whyb = (const float*)d_in[8];
    const float* bhyb = (const float*)d_in[9];

    sent_kernel<<<1024, 256>>>();                      // re-sentinel all replicas each replay
    gemm_kernel<<<dim3(32, 32), 256>>>(sent, emb, Wih, bih, bhh);
    weff_kernel<<<4, 256>>>(Wtag, btag, Whyb, bhyb);
    lstm_kernel<<<NCTA, 256>>>(Whh);
    head_kernel<<<512, 256>>>((float*)d_out);
}

// round 14
// speedup vs baseline: 2.2982x; 1.2264x over previous
#include <cuda_runtime.h>

typedef unsigned long long ull;

#define SEQ 4096
#define HID 1024
#define G4H 4096
#define NCTA 128
#define NREP 16
#define SLOTS 16
#define SENT 0x7FC0DEADu   // NaN payload sentinel: h = o*tanh(c) is never NaN

// ---------------- device scratch (no runtime allocations allowed) ----------------
// g_xg padded by one step so the t+1 prefetch at t=SEQ-1 stays in bounds.
__device__ float g_xg[(size_t)(SEQ + 1) * G4H];       // 64 MB input-gate contributions
__device__ float g_hring[NREP][SLOTS][HID];           // 1 MB L2-RESIDENT sync ring
__device__ float g_hs[(size_t)SEQ * HID];             // 16 MB history (streamed, head only)
__device__ float g_weff[HID];
__device__ float g_beff;

// ---------------- helpers ----------------
__device__ __forceinline__ void ffma2(ull &d, ull a, ull b) {
    asm("fma.rn.f32x2 %0, %1, %2, %0;" : "+l"(d) : "l"(a), "l"(b));
}
__device__ __forceinline__ ull dup2(float x) {
    ull r; asm("mov.b64 %0, {%1, %1};" : "=l"(r) : "f"(x)); return r;
}
__device__ __forceinline__ float2 unp(ull v) {
    float2 r; asm("mov.b64 {%0, %1}, %2;" : "=f"(r.x), "=f"(r.y) : "l"(v)); return r;
}
__device__ __forceinline__ float sigf(float x) {
    return 1.f / (1.f + __expf(-x));
}
__device__ __forceinline__ float tanh_(float x) {
    float e = __expf(-2.f * fabsf(x));
    float t = (1.f - e) / (1.f + e);
    return copysignf(t, x);
}

// ---------------- sentinel fill of the ring (per graph replay; 1 MB) ----------------
__global__ __launch_bounds__(256) void sent_kernel() {
    float4 s;
    s.x = s.y = s.z = s.w = __uint_as_float(SENT);
    float4* p = (float4*)g_hring;
    int n = (NREP * SLOTS * HID) / 4;                 // 64K float4
    for (int i = blockIdx.x * 256 + threadIdx.x; i < n; i += gridDim.x * 256)
        p[i] = s;                                      // plain store: WANT these lines in L2
}

// ---------------- x_gates GEMM: [S,4H] = emb[sent] @ W_ih^T + (b_ih+b_hh) ----
__global__ __launch_bounds__(256, 1) void gemm_kernel(
    const int* __restrict__ sent, const float* __restrict__ emb,
    const float* __restrict__ Wih, const float* __restrict__ bih,
    const float* __restrict__ bhh)
{
    __shared__ __align__(16) float As[16][132];
    __shared__ __align__(16) float Bs[16][132];
    __shared__ int ss[128];

    int tid = threadIdx.x;
    int bn = blockIdx.x * 128;   // gate dim
    int bs = blockIdx.y * 128;   // seq dim
    if (tid < 128) ss[tid] = sent[bs + tid];
    __syncthreads();

    ull acc[8][4] = {};
    int tx = tid & 15, ty = tid >> 4;
    int m0 = ty * 8, n0 = tx * 8;

    for (int k0 = 0; k0 < 1024; k0 += 16) {
#pragma unroll
        for (int p = 0; p < 2; p++) {
            int idx = p * 256 + tid;
            int row = idx >> 2, kq = idx & 3;
            float4 av = *(const float4*)(emb + (size_t)ss[row] * 1024 + k0 + kq * 4);
            As[kq*4+0][row] = av.x; As[kq*4+1][row] = av.y;
            As[kq*4+2][row] = av.z; As[kq*4+3][row] = av.w;
            float4 bv = *(const float4*)(Wih + (size_t)(bn + row) * 1024 + k0 + kq * 4);
            Bs[kq*4+0][row] = bv.x; Bs[kq*4+1][row] = bv.y;
            Bs[kq*4+2][row] = bv.z; Bs[kq*4+3][row] = bv.w;
        }
        __syncthreads();
#pragma unroll
        for (int kk = 0; kk < 16; kk++) {
            float4 aA = *(const float4*)(&As[kk][m0]);
            float4 aB = *(const float4*)(&As[kk][m0 + 4]);
            ulonglong2 b01 = *(const ulonglong2*)(&Bs[kk][n0]);
            ulonglong2 b23 = *(const ulonglong2*)(&Bs[kk][n0 + 4]);
            ull bp0 = b01.x, bp1 = b01.y, bp2 = b23.x, bp3 = b23.y;
            float a[8] = {aA.x, aA.y, aA.z, aA.w, aB.x, aB.y, aB.z, aB.w};
#pragma unroll
            for (int i = 0; i < 8; i++) {
                ull ad = dup2(a[i]);
                ffma2(acc[i][0], ad, bp0);
                ffma2(acc[i][1], ad, bp1);
                ffma2(acc[i][2], ad, bp2);
                ffma2(acc[i][3], ad, bp3);
            }
        }
        __syncthreads();
    }

    float bb[8];
#pragma unroll
    for (int j = 0; j < 8; j++) bb[j] = bih[bn + n0 + j] + bhh[bn + n0 + j];
#pragma unroll
    for (int i = 0; i < 8; i++) {
        float* crow = g_xg + (size_t)(bs + m0 + i) * G4H + bn + n0;
        float2 r0 = unp(acc[i][0]), r1 = unp(acc[i][1]);
        float2 r2 = unp(acc[i][2]), r3 = unp(acc[i][3]);
        float4 v0 = make_float4(r0.x + bb[0], r0.y + bb[1], r1.x + bb[2], r1.y + bb[3]);
        float4 v1 = make_float4(r2.x + bb[4], r2.y + bb[5], r3.x + bb[6], r3.y + bb[7]);
        __stcs((float4*)crow, v0);           // streamed: read exactly once later
        __stcs((float4*)(crow + 4), v1);
    }
}

// ---------------- fold hybrid head: w_eff = W_hyb @ W_tag ----------------
__global__ void weff_kernel(const float* __restrict__ Wtag, const float* __restrict__ btag,
                            const float* __restrict__ Whyb, const float* __restrict__ bhyb)
{
    int h = blockIdx.x * 256 + threadIdx.x;
    float acc = 0.f;
    for (int t = 0; t < 1024; t++) acc += Whyb[t] * Wtag[(size_t)t * 1024 + h];
    g_weff[h] = acc;
    if (h == 0) {
        float b = bhyb[0];
        for (int t = 0; t < 1024; t++) b += Whyb[t] * btag[t];
        g_beff = b;
    }
}

// ---------------- persistent LSTM recurrence (L2-resident ring dataflow sync) -----
// 128 CTAs (<= 148 SMs, one wave). CTA c owns units [8c,8c+8); warp w owns unit
// 8c+w; lane = gate(2b) x K-chunk(3b); 128 W_hh weights/thread in registers.
// Sync: producers publish h[t] into slot t&15 of ALL 16 ring replicas (lanes
// 0-15 in parallel); the 1MB ring never leaves L2, so publish and poll are
// L2-hits (R9's 256MB replica arrays missed to DRAM every step -> 9.3ms).
// Consumer CTA c volatile-polls its quad in replica c&15, slot (t-1)&15:
// detection IS the fetch. Slot recycling: slip between CTAs is <=~1 iteration
// (each CTA polls the FULL h vector, so entering step t implies every CTA
// finished t-1); the 16 designated CTAs (cta<16) re-sentinel the slot holding
// h[t-9] each iteration (issued BEFORE the poll, fire-and-forget) -> >=7-
// iteration margin on both sentinel-vs-reader and sentinel-vs-rewrite.
// h history for the output head goes to g_hs via .cs streaming store (lane
// 16) so the 16MB write-once stream never evicts the ring from L2. x_gates
// is prefetched one FULL step ahead (register-pipelined, .cs).
__global__ __launch_bounds__(256, 1) void lstm_kernel(const float* __restrict__ Whh)
{
    __shared__ __align__(16) float sh_h[2][8 * 132];

    int tid  = threadIdx.x, cta = blockIdx.x;
    int warp = tid >> 5, lane = tid & 31;
    int g    = lane >> 3;          // gate: 0=i 1=f 2=g 3=o
    int kc   = lane & 7;           // K chunk (128 floats each)
    int unit = cta * 8 + warp;
    int wrow = g * 1024 + unit;    // row in W_hh / column in x_gates

    // load this thread's 128 weights into registers (one time)
    ull w[64];
    {
        const ulonglong2* wp = (const ulonglong2*)(Whh + (size_t)wrow * 1024 + kc * 128);
#pragma unroll
        for (int j = 0; j < 32; j++) { ulonglong2 t = wp[j]; w[2*j] = t.x; w[2*j+1] = t.y; }
    }

    const float* xp    = g_xg + wrow;                        // step-t addresses
    const float* pollb = &g_hring[cta & (NREP-1)][0][tid*4]; // poll base (slot stride HID)
    float* sentb       = &g_hring[cta][0][tid*4];            // re-sentinel base (cta<16 only)
    float c = 0.f;                                           // cell state (warp-uniform)
    float* sstore = sh_h[0] + (tid >> 5) * 132 + (tid & 31) * 4;
    // branch-free activation constants: gate g uses tanh, others sigmoid via
    // the shared skeleton r=signed(1-e)/(1+e), act = amul*r + aadd
    float escale = (g == 2) ? -2.f : -1.f;
    float amul   = (g == 2) ? 1.f : 0.5f;
    float aadd   = (g == 2) ? 0.f : 0.5f;
    uint4 sq; sq.x = sq.y = sq.z = sq.w = SENT;

    // prime the xg pipeline: load step 0's value now
    float xgv_cur;
    asm("ld.global.cs.f32 %0, [%1];" : "=f"(xgv_cur) : "l"(xp));
    xp += G4H;

    for (int t = 0; t < SEQ; t++) {
        // issue prefetch for step t+1 (padded array covers t=SEQ-1)
        float xgv_nxt;
        asm("ld.global.cs.f32 %0, [%1];" : "=f"(xgv_nxt) : "l"(xp));
        xp += G4H;

        float dot = 0.f;
        if (t > 0) {
            int buf = t & 1;
            // recycle BEFORE polling (fire-and-forget, overlaps the wait):
            // slot (t+7)&15 holds h[t-9]; its readers finished at iter t-8.
            if (cta < NREP) {
                asm volatile("st.volatile.global.v4.b32 [%0], {%1,%2,%3,%4};"
                             :: "l"(sentb + ((t + 7) & (SLOTS-1)) * HID),
                                "r"(sq.x), "r"(sq.y), "r"(sq.z), "r"(sq.w));
            }
            // poll-on-data: wait for this thread's quad of h[t-1] (L2-hit ring)
            const float* hp_g = pollb + ((t - 1) & (SLOTS-1)) * HID;
            uint4 u;
            do {
                asm volatile("ld.volatile.global.v4.b32 {%0,%1,%2,%3}, [%4];"
                             : "=r"(u.x), "=r"(u.y), "=r"(u.z), "=r"(u.w)
                             : "l"(hp_g));
            } while (u.x == SENT || u.y == SENT || u.z == SENT || u.w == SENT);
            *(uint4*)(sstore + buf * (8 * 132)) = u;
            __syncthreads();

            const ulonglong2* hp = (const ulonglong2*)(sh_h[buf] + kc * 132);
            ull a0 = 0, a1 = 0, a2 = 0, a3 = 0;
#pragma unroll
            for (int j = 0; j < 32; j += 2) {
                ulonglong2 h0 = hp[j];
                ulonglong2 h1 = hp[j + 1];
                ffma2(a0, w[2*j],     h0.x);
                ffma2(a1, w[2*j + 1], h0.y);
                ffma2(a2, w[2*j + 2], h1.x);
                ffma2(a3, w[2*j + 3], h1.y);
            }
            float2 f0 = unp(a0), f1 = unp(a1), f2 = unp(a2), f3 = unp(a3);
            dot = ((f0.x + f0.y) + (f1.x + f1.y)) + ((f2.x + f2.y) + (f3.x + f3.y));
        }

        // reduce across the 8 K-chunk lanes; every lane of a gate group ends
        // with the full gate pre-activation
        dot += __shfl_xor_sync(0xffffffffu, dot, 1);
        dot += __shfl_xor_sync(0xffffffffu, dot, 2);
        dot += __shfl_xor_sync(0xffffffffu, dot, 4);
        dot += xgv_cur;

        // branch-free activation (uniform within each 8-lane gate group)
        float e = __expf(escale * fabsf(dot));
        float r = copysignf((1.f - e) / (1.f + e), dot);
        float act = fmaf(amul, r, aadd);

        // gather the 4 gate activations (any lane of each group is valid)
        float a_i = __shfl_sync(0xffffffffu, act, kc);
        float a_f = __shfl_sync(0xffffffffu, act, kc + 8);
        float a_g = __shfl_sync(0xffffffffu, act, kc + 16);
        float a_o = __shfl_sync(0xffffffffu, act, kc + 24);

        // cell update, redundantly in all lanes (identical values)
        c = a_f * c + a_i * a_g;
        float h = a_o * tanh_(c);

        // publish: lanes 0-15 -> ring replicas (parallel, L2-hit);
        //          lane 16   -> history for the output head (.cs stream)
        if (lane < NREP) {
            asm volatile("st.volatile.global.f32 [%0], %1;"
                         :: "l"(&g_hring[lane][t & (SLOTS-1)][unit]), "f"(h));
        } else if (lane == NREP) {
            __stcs(&g_hs[(size_t)t * HID + unit], h);
        }

        xgv_cur = xgv_nxt;
        // no trailing barrier: next step writes the OTHER smem buffer
    }
}

// ---------------- output head: sigmoid(hs . w_eff + b_eff) ----------------
__global__ __launch_bounds__(256) void head_kernel(float* __restrict__ out)
{
    int warp = (blockIdx.x * 256 + threadIdx.x) >> 5;
    int lane = threadIdx.x & 31;
    const float* hrow = g_hs + (size_t)warp * HID;
    float acc = 0.f;
#pragma unroll
    for (int i = 0; i < 32; i++) acc += hrow[lane + 32 * i] * g_weff[lane + 32 * i];
#pragma unroll
    for (int o = 16; o; o >>= 1) acc += __shfl_xor_sync(0xffffffffu, acc, o);
    if (lane == 0) out[warp] = sigf(acc + g_beff);
}

// ---------------- launcher ----------------
extern "C" void kernel_launch(void* const* d_in, const int* in_sizes, int n_in,
                              void* d_out, int out_size)
{
    const int*   sent = (const int*)d_in[0];
    const float* emb  = (const float*)d_in[1];
    const float* Wih  = (const float*)d_in[2];
    const float* Whh  = (const float*)d_in[3];
    const float* bih  = (const float*)d_in[4];
    const float* bhh  = (const float*)d_in[5];
    const float* Wtag = (const float*)d_in[6];
    const float* btag = (const float*)d_in[7];
    const float* Whyb = (const float*)d_in[8];
    const float* bhyb = (const float*)d_in[9];

    sent_kernel<<<64, 256>>>();                        // re-sentinel the 1 MB ring
    gemm_kernel<<<dim3(32, 32), 256>>>(sent, emb, Wih, bih, bhh);
    weff_kernel<<<4, 256>>>(Wtag, btag, Whyb, bhyb);
    lstm_kernel<<<NCTA, 256>>>(Whh);
    head_kernel<<<512, 256>>>((float*)d_out);
}